// round 17
// baseline (speedup 1.0000x reference)
#include <cuda_runtime.h>
#include <math.h>

#define NVOX 120000
#define EPSV 1e-5f

// ---------------- scratch (no dynamic alloc allowed) ----------------
__device__ __align__(16) float g_bufA[NVOX * 64];
__device__ __align__(16) float g_bufB[NVOX * 64];
__device__ __align__(16) float g_bufC[NVOX * 64];
__device__ __align__(16) float g_bufD[NVOX * 64];
__device__ __align__(16) float g_bufE[NVOX * 64];
__device__ float g_sum[7 * 64];
__device__ float g_sq [7 * 64];
__device__ int g_permA[NVOX];
__device__ int g_permB[NVOX];
__device__ int g_maskA[NVOX];
__device__ int g_maskB[NVOX];
__device__ int g_histA[512];
__device__ int g_histB[512];
__device__ int g_ctrA[512];
__device__ int g_ctrB[512];

// ---------------- packed f32x2 helpers ----------------
__device__ __forceinline__ unsigned long long pack2same(float v) {
    unsigned long long r;
    asm("mov.b64 %0, {%1, %1};" : "=l"(r) : "f"(v));
    return r;
}
__device__ __forceinline__ void unpack2(float& lo, float& hi, unsigned long long a) {
    asm("mov.b64 {%0, %1}, %2;" : "=f"(lo), "=f"(hi) : "l"(a));
}
__device__ __forceinline__ void ffma2(unsigned long long& d, unsigned long long a, unsigned long long b) {
    asm("fma.rn.f32x2 %0, %1, %2, %0;" : "+l"(d) : "l"(a), "l"(b));
}
__device__ __forceinline__ unsigned long long add2(unsigned long long a, unsigned long long b) {
    unsigned long long r;
    asm("add.rn.f32x2 %0, %1, %2;" : "=l"(r) : "l"(a), "l"(b));
    return r;
}
__device__ __forceinline__ unsigned long long mul2(unsigned long long a, unsigned long long b) {
    unsigned long long r;
    asm("mul.rn.f32x2 %0, %1, %2;" : "=l"(r) : "l"(a), "l"(b));
    return r;
}

template <int CT>
__device__ __forceinline__ void mac_row(unsigned long long* acc, float v, const float* w) {
    unsigned long long vv = pack2same(v);
    const ulonglong2* w2 = reinterpret_cast<const ulonglong2*>(w);
#pragma unroll
    for (int q = 0; q < CT / 4; q++) {
        ulonglong2 ww = w2[q];
        ffma2(acc[2 * q + 0], vv, ww.x);
        ffma2(acc[2 * q + 1], vv, ww.y);
    }
}

__device__ __forceinline__ float lrelu(float x) { return x > 0.f ? x : 0.01f * x; }

__device__ __forceinline__ float to_tf32(float x) {
    float r;
    asm("cvt.rna.tf32.f32 %0, %1;" : "=f"(r) : "f"(x));
    return r;
}

__device__ __forceinline__ void mma_tf32(float* c, const unsigned* a, unsigned b0, unsigned b1) {
    asm("mma.sync.aligned.m16n8k8.row.col.f32.tf32.tf32.f32 "
        "{%0,%1,%2,%3}, {%4,%5,%6,%7}, {%8,%9}, {%0,%1,%2,%3};"
        : "+f"(c[0]), "+f"(c[1]), "+f"(c[2]), "+f"(c[3])
        : "r"(a[0]), "r"(a[1]), "r"(a[2]), "r"(a[3]), "r"(b0), "r"(b1));
}

// ================= node 1: mask histogram (+ zero SUM/SQ) ==================
// hist/ctr are zeroed by the LAST node of the previous call/replay (combine).
__global__ void mask_hist_kernel(const int* __restrict__ nbrA, const int* __restrict__ nbrB,
                                 int n, int* __restrict__ histA, int* __restrict__ histB,
                                 int* __restrict__ masksA, int* __restrict__ masksB,
                                 float* __restrict__ sum, float* __restrict__ sq) {
    if (blockIdx.x == 0 && blockIdx.y == 0) {
        for (int i = threadIdx.x; i < 7 * 64; i += blockDim.x) { sum[i] = 0.f; sq[i] = 0.f; }
    }
    const int* nbr = blockIdx.y ? nbrB : nbrA;
    int* hist      = blockIdx.y ? histB : histA;
    int* masks     = blockIdx.y ? masksB : masksA;
    __shared__ int lh[512];
    for (int i = threadIdx.x; i < 512; i += blockDim.x) lh[i] = 0;
    __syncthreads();
    int r = blockIdx.x * blockDim.x + threadIdx.x;
    if (r < n) {
        const int* nb = nbr + (size_t)r * 9;
        int m = 0;
#pragma unroll
        for (int k = 0; k < 9; k++) m |= (nb[k] < n) << k;
        masks[r] = m;
        atomicAdd(&lh[m], 1);
    }
    __syncthreads();
    for (int i = threadIdx.x; i < 512; i += blockDim.x)
        if (lh[i]) atomicAdd(&hist[i], lh[i]);
}

// ================= node 2: scatter with block-local scan ===================
__global__ void scatter_kernel(const int* __restrict__ masksA, const int* __restrict__ masksB,
                               int n, const int* __restrict__ histA, const int* __restrict__ histB,
                               int* __restrict__ ctrA, int* __restrict__ ctrB,
                               int* __restrict__ permA, int* __restrict__ permB) {
    const int* masks = blockIdx.y ? masksB : masksA;
    const int* hist  = blockIdx.y ? histB : histA;
    int* ctr         = blockIdx.y ? ctrB : ctrA;
    int* perm        = blockIdx.y ? permB : permA;
    __shared__ int tmp[512];
    __shared__ int sc[512];
    int t = threadIdx.x;
    tmp[t] = hist[t];
    __syncthreads();
    for (int off = 1; off < 512; off <<= 1) {
        int add = (t >= off) ? tmp[t - off] : 0;
        __syncthreads();
        tmp[t] += add;
        __syncthreads();
    }
    sc[t] = (t == 0) ? 0 : tmp[t - 1];
    __syncthreads();

    int r = blockIdx.x * 512 + t;
    int lane = t & 31;
    int m = (r < n) ? masks[r] : -1;
    unsigned grp = __match_any_sync(0xffffffffu, m);
    int leader = __ffs(grp) - 1;
    int rank = __popc(grp & ((1u << lane) - 1u));
    int base = 0;
    if (lane == leader && m >= 0) base = sc[m] + atomicAdd(&ctr[m], __popc(grp));
    base = __shfl_sync(0xffffffffu, base, leader);
    if (m >= 0) perm[base + rank] = r;
}

// ============ conv body: dense tf32 GEMM + sparse fp32 gather ==============
template <int CIN, int COUT, bool AFF, bool COMB, bool STATS>
__device__ __forceinline__ void
fused_conv_body(float* sm,
                const float* __restrict__ in, const float* __restrict__ in2,
                const int* __restrict__ nbr,
                const int* __restrict__ perm, const int* __restrict__ hist,
                const float* __restrict__ W,
                const float* __restrict__ ps1, const float* __restrict__ pq1,
                const float* __restrict__ g1, const float* __restrict__ b1,
                const float* __restrict__ ps2, const float* __restrict__ pq2,
                const float* __restrict__ g2, const float* __restrict__ b2,
                float* __restrict__ out, float* __restrict__ osum, float* __restrict__ osq,
                int n, int ntiles, int DB, int SBX) {
    const int tid = threadIdx.x;
    const int B16 = __ldg(hist + 16);
    const float inv_n = 1.0f / (float)n;

    if ((int)blockIdx.x < DB) {
        // ---------------- dense GEMM path ----------------
        constexpr int MX = (CIN > COUT) ? CIN : COUT;
        constexpr int SP = MX + 4;
        constexpr int WP = COUT + 1;
        float* wsm = sm;                    // CIN*WP (tf32)
        float* stg = wsm + CIN * WP;        // 8 warps * 16 * SP
        float* csc = stg + 8 * 16 * SP;     // CIN
        float* csh = csc + CIN;             // CIN
        float* csc2 = csh + CIN;            // CIN
        float* csh2 = csc2 + CIN;           // CIN
        const int wid = tid >> 5, lane = tid & 31;
        const int gr = lane >> 2, tg = lane & 3;

        if (AFF || COMB) {
            for (int i = tid; i < CIN; i += 256) {
                float m   = ps1[i] * inv_n;
                float var = pq1[i] * inv_n - m * m;
                float s   = g1[i] / sqrtf(var + EPSV);
                csc[i] = s; csh[i] = b1[i] - m * s;
            }
        }
        if (COMB) {
            for (int i = tid; i < CIN; i += 256) {
                float m   = ps2[i] * inv_n;
                float var = pq2[i] * inv_n - m * m;
                float s   = g2[i] / sqrtf(var + EPSV);
                csc2[i] = s; csh2[i] = b2[i] - m * s;
            }
        }
        {   // stage center weight slice (k=4), tf32-converted
            const float* Wc = W + 4 * CIN * COUT;
            for (int i = tid; i < CIN * COUT; i += 256) {
                int k = i / COUT, nn = i - k * COUT;
                wsm[k * WP + nn] = to_tf32(Wc[i]);
            }
        }
        __syncthreads();
        float* aw = stg + wid * 16 * SP;

        float s0 = 0.f, q0 = 0.f, s1 = 0.f, q1 = 0.f;

        for (int base = blockIdx.x * 128; base < B16; base += DB * 128) {
            const int wbase = base + wid * 16;
            if (wbase >= B16) continue;
            __syncwarp();
            int prow = -1;
            if (lane < 16 && wbase + lane < B16) prow = perm[wbase + lane];

#pragma unroll
            for (int it = 0; it < CIN / 8; it++) {
                int e = it * 32 + lane;
                int r = e / (CIN / 4), c4 = e - r * (CIN / 4);
                int pr = __shfl_sync(0xffffffffu, prow, r);
                float4 v = make_float4(0.f, 0.f, 0.f, 0.f);
                if (pr >= 0) {
                    v = *reinterpret_cast<const float4*>(in + (size_t)pr * CIN + 4 * c4);
                    if (AFF || COMB) {
                        v.x = fmaf(v.x, csc[4 * c4 + 0], csh[4 * c4 + 0]);
                        v.y = fmaf(v.y, csc[4 * c4 + 1], csh[4 * c4 + 1]);
                        v.z = fmaf(v.z, csc[4 * c4 + 2], csh[4 * c4 + 2]);
                        v.w = fmaf(v.w, csc[4 * c4 + 3], csh[4 * c4 + 3]);
                    }
                    if (COMB) {
                        float4 u = *reinterpret_cast<const float4*>(in2 + (size_t)pr * CIN + 4 * c4);
                        v.x += fmaf(u.x, csc2[4 * c4 + 0], csh2[4 * c4 + 0]);
                        v.y += fmaf(u.y, csc2[4 * c4 + 1], csh2[4 * c4 + 1]);
                        v.z += fmaf(u.z, csc2[4 * c4 + 2], csh2[4 * c4 + 2]);
                        v.w += fmaf(u.w, csc2[4 * c4 + 3], csh2[4 * c4 + 3]);
                    }
                }
                v.x = to_tf32(v.x); v.y = to_tf32(v.y); v.z = to_tf32(v.z); v.w = to_tf32(v.w);
                *reinterpret_cast<float4*>(aw + r * SP + 4 * c4) = v;
            }
            __syncwarp();

            unsigned af[CIN / 8][4];
#pragma unroll
            for (int kt = 0; kt < CIN / 8; kt++) {
                const float* r0 = aw + gr * SP + kt * 8 + tg;
                const float* r1 = aw + (gr + 8) * SP + kt * 8 + tg;
                af[kt][0] = __float_as_uint(r0[0]);
                af[kt][1] = __float_as_uint(r1[0]);
                af[kt][2] = __float_as_uint(r0[4]);
                af[kt][3] = __float_as_uint(r1[4]);
            }

            float cf[COUT / 8][4];
#pragma unroll
            for (int nt = 0; nt < COUT / 8; nt++) {
                cf[nt][0] = cf[nt][1] = cf[nt][2] = cf[nt][3] = 0.f;
#pragma unroll
                for (int kt = 0; kt < CIN / 8; kt++) {
                    unsigned b0 = __float_as_uint(wsm[(kt * 8 + tg) * WP + nt * 8 + gr]);
                    unsigned b1v = __float_as_uint(wsm[(kt * 8 + tg + 4) * WP + nt * 8 + gr]);
                    mma_tf32(cf[nt], af[kt], b0, b1v);
                }
            }
            __syncwarp();

#pragma unroll
            for (int nt = 0; nt < COUT / 8; nt++) {
                int col = nt * 8 + 2 * tg;
                aw[gr * SP + col]           = lrelu(cf[nt][0]);
                aw[gr * SP + col + 1]       = lrelu(cf[nt][1]);
                aw[(gr + 8) * SP + col]     = lrelu(cf[nt][2]);
                aw[(gr + 8) * SP + col + 1] = lrelu(cf[nt][3]);
            }
            __syncwarp();

            if (STATS) {
                // invalid rows hold exact zeros -> contribute nothing
#pragma unroll
                for (int r = 0; r < 16; r++) {
                    float v = aw[r * SP + lane];
                    s0 += v; q0 += v * v;
                    if (COUT == 64) {
                        float w = aw[r * SP + 32 + lane];
                        s1 += w; q1 += w * w;
                    }
                }
            }

#pragma unroll
            for (int it = 0; it < COUT / 8; it++) {
                int e = it * 32 + lane;
                int r = e / (COUT / 4), c4 = e - r * (COUT / 4);
                int pr = __shfl_sync(0xffffffffu, prow, r);
                if (pr >= 0)
                    *reinterpret_cast<float4*>(out + (size_t)pr * COUT + 4 * c4) =
                        *reinterpret_cast<const float4*>(aw + r * SP + 4 * c4);
            }
        }

        if (STATS) {
            atomicAdd(osum + lane, s0);
            atomicAdd(osq + lane, q0);
            if (COUT == 64) {
                atomicAdd(osum + 32 + lane, s1);
                atomicAdd(osq + 32 + lane, q1);
            }
        }
    } else {
        // ---------------- sparse gather path (CT = 16) ----------------
        constexpr int CT = 16;
        float* ws  = sm;                    // 9*CIN*CT
        float* csc = ws + 9 * CIN * CT;
        float* csh = csc + CIN;
        float* csc2 = csh + CIN;
        float* csh2 = csc2 + CIN;
        const int lane = tid & 31;
        const int s = blockIdx.x - DB;
        const int tbi = s / SBX;
        const int sx  = s - tbi * SBX;
        const int tb  = tbi * CT;

        {
            float4* ws4 = reinterpret_cast<float4*>(ws);
            const float4* W4 = reinterpret_cast<const float4*>(W);
            const int tb4 = tb >> 2;
            const int c4w = COUT >> 2;
            constexpr int TOT4 = 9 * CIN * CT / 4;
            constexpr int Q4 = CT / 4;
#pragma unroll 4
            for (int i = tid; i < TOT4; i += 256) {
                int r = i / Q4;
                int q = i - r * Q4;
                ws4[i] = W4[r * c4w + tb4 + q];
            }
        }
        if (AFF || COMB) {
            for (int i = tid; i < CIN; i += 256) {
                float m   = ps1[i] * inv_n;
                float var = pq1[i] * inv_n - m * m;
                float sc  = g1[i] / sqrtf(var + EPSV);
                csc[i] = sc; csh[i] = b1[i] - m * sc;
            }
        }
        if (COMB) {
            for (int i = tid; i < CIN; i += 256) {
                float m   = ps2[i] * inv_n;
                float var = pq2[i] * inv_n - m * m;
                float sc  = g2[i] / sqrtf(var + EPSV);
                csc2[i] = sc; csh2[i] = b2[i] - m * sc;
            }
        }
        __syncthreads();

        unsigned long long accS = 0ull, accQ = 0ull;
        const int t0 = B16 >> 8;
        for (int t = t0 + sx; t < ntiles; t += SBX) {
            const int gid = t * 256 + tid;
            const bool rok = (gid < n) && (gid >= B16);
            const int row = rok ? perm[gid] : 0;

            const int* nb = nbr + (size_t)row * 9;
            int idx[9];
#pragma unroll
            for (int k = 0; k < 9; k++) idx[k] = rok ? __ldg(nb + k) : n;

            unsigned long long acc[CT / 2];
#pragma unroll
            for (int i = 0; i < CT / 2; i++) acc[i] = 0ull;

#pragma unroll
            for (int k = 0; k < 9; k++) {
                const int j = idx[k];
                const bool v = j < n;
                if (!__any_sync(0xffffffffu, v)) continue;
                const float4* xr = reinterpret_cast<const float4*>(in + (size_t)j * CIN);
                const float4* xr2 = COMB ? reinterpret_cast<const float4*>(in2 + (size_t)j * CIN) : nullptr;
                const float* wk = ws + k * CIN * CT;
#pragma unroll
                for (int c4 = 0; c4 < CIN / 4; c4++) {
                    float4 val = make_float4(0.f, 0.f, 0.f, 0.f);
                    if (v) {
                        val = xr[c4];
                        if (AFF || COMB) {
                            val.x = fmaf(val.x, csc[4 * c4 + 0], csh[4 * c4 + 0]);
                            val.y = fmaf(val.y, csc[4 * c4 + 1], csh[4 * c4 + 1]);
                            val.z = fmaf(val.z, csc[4 * c4 + 2], csh[4 * c4 + 2]);
                            val.w = fmaf(val.w, csc[4 * c4 + 3], csh[4 * c4 + 3]);
                        }
                        if (COMB) {
                            float4 u = xr2[c4];
                            val.x += fmaf(u.x, csc2[4 * c4 + 0], csh2[4 * c4 + 0]);
                            val.y += fmaf(u.y, csc2[4 * c4 + 1], csh2[4 * c4 + 1]);
                            val.z += fmaf(u.z, csc2[4 * c4 + 2], csh2[4 * c4 + 2]);
                            val.w += fmaf(u.w, csc2[4 * c4 + 3], csh2[4 * c4 + 3]);
                        }
                    }
                    const float* w0 = wk + (4 * c4) * CT;
                    mac_row<CT>(acc, val.x, w0);
                    mac_row<CT>(acc, val.y, w0 + CT);
                    mac_row<CT>(acc, val.z, w0 + 2 * CT);
                    mac_row<CT>(acc, val.w, w0 + 3 * CT);
                }
            }

            // lrelu, store, butterfly-stats (invalid rows -> zeros)
            float* o = out + (size_t)row * COUT + tb;
#pragma unroll
            for (int i = 0; i < CT / 2; i++) {
                float lo, hi;
                unpack2(lo, hi, acc[i]);
                lo = lrelu(lo); hi = lrelu(hi);
                unsigned long long pv;
                asm("mov.b64 %0, {%1, %2};" : "=l"(pv) : "f"(lo), "f"(hi));
                acc[i] = pv;
                if (rok) reinterpret_cast<float2*>(o)[i] = make_float2(lo, hi);
            }

            if (STATS) {
#pragma unroll
                for (int i = 0; i < CT / 2; i++) {
                    unsigned long long v = acc[i];
                    unsigned long long q = mul2(v, v);
#pragma unroll
                    for (int m = 16; m; m >>= 1) {
                        v = add2(v, __shfl_xor_sync(0xffffffffu, v, m));
                        q = add2(q, __shfl_xor_sync(0xffffffffu, q, m));
                    }
                    if (lane == i) accS = add2(accS, v);
                    if (lane == 16 + i) accQ = add2(accQ, q);
                }
            }
        }

        if (STATS) {
            if (lane < 8) {
                float lo, hi;
                unpack2(lo, hi, accS);
                atomicAdd(osum + tb + 2 * lane, lo);
                atomicAdd(osum + tb + 2 * lane + 1, hi);
            }
            if (lane >= 16 && lane < 24) {
                float lo, hi;
                unpack2(lo, hi, accQ);
                atomicAdd(osq + tb + 2 * (lane - 16), lo);
                atomicAdd(osq + tb + 2 * (lane - 16) + 1, hi);
            }
        }
    }
}

// dual-problem wrapper: blockIdx.y selects the conv problem
template <int CIN, int COUT, bool AF1, bool CB1, bool ST1, bool AF2, bool CB2, bool ST2>
__global__ void __launch_bounds__(256)
fused_conv_dual(const float* in1, const float* in1b, const int* nbr1, const int* perm1, const int* hist1,
                const float* W1, const float* ps1a, const float* pq1a, const float* g1a, const float* b1a,
                const float* ps1b, const float* pq1b, const float* g1b, const float* b1b,
                float* out1, float* osum1, float* osq1,
                const float* in2, const float* in2b, const int* nbr2, const int* perm2, const int* hist2,
                const float* W2, const float* ps2a, const float* pq2a, const float* g2a, const float* b2a,
                const float* ps2b, const float* pq2b, const float* g2b, const float* b2b,
                float* out2, float* osum2, float* osq2,
                int n, int ntiles, int DB, int SBX) {
    extern __shared__ __align__(16) float sm[];
    if (blockIdx.y == 0)
        fused_conv_body<CIN, COUT, AF1, CB1, ST1>(sm, in1, in1b, nbr1, perm1, hist1, W1,
            ps1a, pq1a, g1a, b1a, ps1b, pq1b, g1b, b1b, out1, osum1, osq1, n, ntiles, DB, SBX);
    else
        fused_conv_body<CIN, COUT, AF2, CB2, ST2>(sm, in2, in2b, nbr2, perm2, hist2, W2,
            ps2a, pq2a, g2a, b2a, ps2b, pq2b, g2b, b2b, out2, osum2, osq2, n, ntiles, DB, SBX);
}

// ---------------- out = bnA(a) + bnB(b); bn from SUM/SQ in prologue --------
// Block 0 also zeroes hist/ctr for the NEXT call/replay.
template <int C>
__global__ void combine_kernel(const float* __restrict__ a,
                               const float* __restrict__ suma, const float* __restrict__ sqa,
                               const float* __restrict__ ga, const float* __restrict__ ba,
                               const float* __restrict__ bsrc,
                               const float* __restrict__ sumb, const float* __restrict__ sqb,
                               const float* __restrict__ gb, const float* __restrict__ bb,
                               float* __restrict__ o, int n,
                               int* __restrict__ hA, int* __restrict__ hB,
                               int* __restrict__ cA, int* __restrict__ cB) {
    if (blockIdx.x == 0) {
        for (int i = threadIdx.x; i < 512; i += blockDim.x) {
            hA[i] = 0; hB[i] = 0; cA[i] = 0; cB[i] = 0;
        }
    }
    __shared__ float sA[C], hAa[C], sB[C], hBb[C];
    const float inv_n = 1.0f / (float)n;
    for (int i = threadIdx.x; i < C; i += blockDim.x) {
        float m   = suma[i] * inv_n;
        float var = sqa[i] * inv_n - m * m;
        float s   = ga[i] / sqrtf(var + EPSV);
        sA[i] = s; hAa[i] = ba[i] - m * s;
        m   = sumb[i] * inv_n;
        var = sqb[i] * inv_n - m * m;
        s   = gb[i] / sqrtf(var + EPSV);
        sB[i] = s; hBb[i] = bb[i] - m * s;
    }
    __syncthreads();
    const int total = n * C;
    for (int i = blockIdx.x * blockDim.x + threadIdx.x; i < total; i += gridDim.x * blockDim.x) {
        int c = i & (C - 1);
        o[i] = fmaf(a[i], sA[c], hAa[c]) + fmaf(bsrc[i], sB[c], hBb[c]);
    }
}

// ---------------- host ----------------
static constexpr size_t smem_fused(int cin, int cout) {
    int mx = cin > cout ? cin : cout;
    size_t gemm = (size_t)(cin * (cout + 1) + 8 * 16 * (mx + 4) + 4 * cin) * sizeof(float);
    size_t sparse = (size_t)(9 * cin * 16 + 4 * cin) * sizeof(float);
    return gemm > sparse ? gemm : sparse;
}

struct GridShape { int total, DB, SBX; };

template <typename K>
static GridShape shape_grid(K kern, size_t smem, int nt) {
    int occ = 0;
    cudaFuncSetAttribute((const void*)kern, cudaFuncAttributeMaxDynamicSharedMemorySize, (int)smem);
    cudaOccupancyMaxActiveBlocksPerMultiprocessor(&occ, kern, 256, smem);
    if (occ < 1) occ = 1;
    int X = (occ * 148) / 2;              // per y-slice, exactly one wave total
    if (X < 1 + nt) X = 1 + nt;
    int SBX = (X * 7) / (15 * nt);        // ~47% of slots to sparse
    if (SBX < 1) SBX = 1;
    int DB = X - SBX * nt;                // dense absorbs rounding
    if (DB < 1) { DB = 1; SBX = (X - 1) / nt; if (SBX < 1) SBX = 1; }
    GridShape g; g.total = DB + SBX * nt; g.DB = DB; g.SBX = SBX;
    return g;
}

extern "C" void kernel_launch(void* const* d_in, const int* in_sizes, int n_in,
                              void* d_out, int out_size) {
    const float* x      = (const float*)d_in[0];
    const int*   nbr133 = (const int*)  d_in[1];
    const int*   nbr313 = (const int*)  d_in[2];
    const float* W_c1   = (const float*)d_in[3];
    const float* g0     = (const float*)d_in[4];
    const float* b0     = (const float*)d_in[5];
    const float* W_c12  = (const float*)d_in[6];
    const float* g02    = (const float*)d_in[7];
    const float* b02    = (const float*)d_in[8];
    const float* W_c2   = (const float*)d_in[9];
    const float* W_c3   = (const float*)d_in[10];
    const float* g2     = (const float*)d_in[11];
    const float* b2     = (const float*)d_in[12];
    const float* W_r1   = (const float*)d_in[13];
    const float* rg0    = (const float*)d_in[14];
    const float* rb0    = (const float*)d_in[15];
    const float* W_r12  = (const float*)d_in[16];
    const float* rg02   = (const float*)d_in[17];
    const float* rb02   = (const float*)d_in[18];
    const float* W_r2   = (const float*)d_in[19];
    const float* rg1    = (const float*)d_in[20];
    const float* rb1    = (const float*)d_in[21];
    const float* W_r3   = (const float*)d_in[22];
    const float* rg2    = (const float*)d_in[23];
    const float* rb2    = (const float*)d_in[24];
    float* out = (float*)d_out;

    const int n = in_sizes[0] / 16;   // 120000

    float *BA, *BB, *BC, *BD, *BE, *SUM, *SQ;
    int *PA, *PB, *MA, *MB, *HA, *HB, *CA, *CB;
    cudaGetSymbolAddress((void**)&BA,  g_bufA);
    cudaGetSymbolAddress((void**)&BB,  g_bufB);
    cudaGetSymbolAddress((void**)&BC,  g_bufC);
    cudaGetSymbolAddress((void**)&BD,  g_bufD);
    cudaGetSymbolAddress((void**)&BE,  g_bufE);
    cudaGetSymbolAddress((void**)&SUM, g_sum);
    cudaGetSymbolAddress((void**)&SQ,  g_sq);
    cudaGetSymbolAddress((void**)&PA,  g_permA);
    cudaGetSymbolAddress((void**)&PB,  g_permB);
    cudaGetSymbolAddress((void**)&MA,  g_maskA);
    cudaGetSymbolAddress((void**)&MB,  g_maskB);
    cudaGetSymbolAddress((void**)&HA,  g_histA);
    cudaGetSymbolAddress((void**)&HB,  g_histB);
    cudaGetSymbolAddress((void**)&CA,  g_ctrA);
    cudaGetSymbolAddress((void**)&CB,  g_ctrB);

    // occupancy-shaped single-wave grids (computed once)
    static GridShape gs3 = {0, 0, 0}, gs4 = {0, 0, 0}, gs5 = {0, 0, 0}, gs6 = {0, 0, 0};
    if (gs3.total == 0) {
        gs3 = shape_grid(fused_conv_dual<16, 32, false, false, true, false, false, false>, smem_fused(16, 32), 2);
        gs4 = shape_grid(fused_conv_dual<32, 32, true,  false, true, false, false, true >, smem_fused(32, 32), 2);
        gs5 = shape_grid(fused_conv_dual<32, 64, false, true,  true, false, true,  true >, smem_fused(32, 64), 4);
        gs6 = shape_grid(fused_conv_dual<64, 64, true,  false, true, true,  false, true >, smem_fused(64, 64), 4);
    }

    const int TB = 256;
    const int ntiles = (n + TB - 1) / TB;
    const int G = ntiles;

    // ----- node 1: hist (+ zero SUM/SQ) -----
    mask_hist_kernel<<<dim3(G, 2), TB>>>(nbr133, nbr313, n, HA, HB, MA, MB, SUM, SQ);
    // ----- node 2: scatter (block-local scan) -----
    scatter_kernel<<<dim3((n + 511) / 512, 2), 512>>>(MA, MB, n, HA, HB, CA, CB, PA, PB);

    // ===== node 3: c1 (x,133 -> BA, stats SUM0) || c2 (x,313 -> BC) =====
    fused_conv_dual<16, 32, false, false, true, false, false, false>
        <<<dim3(gs3.total, 2), TB, smem_fused(16, 32)>>>(
        x, nullptr, nbr133, PA, HA, W_c1,
        nullptr, nullptr, nullptr, nullptr, nullptr, nullptr, nullptr, nullptr,
        BA, SUM + 0, SQ + 0,
        x, nullptr, nbr313, PB, HB, W_c2,
        nullptr, nullptr, nullptr, nullptr, nullptr, nullptr, nullptr, nullptr,
        BC, nullptr, nullptr,
        n, ntiles, gs3.DB, gs3.SBX);

    // ===== node 4: c12 (aff0(BA),313 -> BB, stats SUM64) || c3 (BC,133 -> BD, stats SUM128) =====
    fused_conv_dual<32, 32, true, false, true, false, false, true>
        <<<dim3(gs4.total, 2), TB, smem_fused(32, 32)>>>(
        BA, nullptr, nbr313, PB, HB, W_c12,
        SUM + 0, SQ + 0, g0, b0, nullptr, nullptr, nullptr, nullptr,
        BB, SUM + 64, SQ + 64,
        BC, nullptr, nbr133, PA, HA, W_c3,
        nullptr, nullptr, nullptr, nullptr, nullptr, nullptr, nullptr, nullptr,
        BD, SUM + 128, SQ + 128,
        n, ntiles, gs4.DB, gs4.SBX);

    // ===== node 5: y = bn2(BD)+bn1(BB) fused into r1/r2 gather =====
    fused_conv_dual<32, 64, false, true, true, false, true, true>
        <<<dim3(gs5.total, 2), TB, smem_fused(32, 64)>>>(
        BD, BB, nbr313, PB, HB, W_r1,
        SUM + 128, SQ + 128, g2, b2, SUM + 64, SQ + 64, g02, b02,
        BA, SUM + 192, SQ + 192,
        BD, BB, nbr133, PA, HA, W_r2,
        SUM + 128, SQ + 128, g2, b2, SUM + 64, SQ + 64, g02, b02,
        BE, SUM + 320, SQ + 320,
        n, ntiles, gs5.DB, gs5.SBX);

    // ===== node 6: r12 (aff3(BA),133 -> BB, stats SUM256) || r3 (aff5(BE),313 -> BD, stats SUM384) =====
    fused_conv_dual<64, 64, true, false, true, true, false, true>
        <<<dim3(gs6.total, 2), TB, smem_fused(64, 64)>>>(
        BA, nullptr, nbr133, PA, HA, W_r12,
        SUM + 192, SQ + 192, rg0, rb0, nullptr, nullptr, nullptr, nullptr,
        BB, SUM + 256, SQ + 256,
        BE, nullptr, nbr313, PB, HB, W_r3,
        SUM + 320, SQ + 320, rg1, rb1, nullptr, nullptr, nullptr, nullptr,
        BD, SUM + 384, SQ + 384,
        n, ntiles, gs6.DB, gs6.SBX);

    // ===== node 7: out = bn6(BD) + bn4(BB); zero hist/ctr for next replay =====
    combine_kernel<64><<<1184, 256>>>(BD, SUM + 384, SQ + 384, rg2, rb2,
                                      BB, SUM + 256, SQ + 256, rg02, rb02, out, n,
                                      HA, HB, CA, CB);
}